// round 1
// baseline (speedup 1.0000x reference)
#include <cuda_runtime.h>
#include <cuda_bf16.h>
#include <stdint.h>

#define KLAB 256
#define DPAIRS 128   // 128 bf16x2 pairs (i-rows) per column

// D matrix, bf16x2-packed: g_Dp[k*KLAB + j] holds (expm1(trans[2k][j]), expm1(trans[2k+1][j]))
__device__ uint32_t g_Dp[DPAIRS * KLAB];
__device__ float    g_path[64];

static __device__ __forceinline__ __nv_bfloat162 as_bf2(uint32_t u) {
    return *reinterpret_cast<__nv_bfloat162*>(&u);
}

// ---------------- prep: D = expm1(trans), packed bf16x2, k-major for coalesced column loads
__global__ void prep_kernel(const float* __restrict__ trans) {
    int idx = blockIdx.x * blockDim.x + threadIdx.x;   // 32768 total
    if (idx >= DPAIRS * KLAB) return;
    int k = idx >> 8;        // pair index (rows 2k, 2k+1)
    int j = idx & (KLAB - 1);
    float a = expm1f(trans[(2 * k) * KLAB + j]);
    float b = expm1f(trans[(2 * k + 1) * KLAB + j]);
    __nv_bfloat162 d2 = __floats2bfloat162_rn(a, b);   // .x = row 2k (low half)
    g_Dp[idx] = *reinterpret_cast<uint32_t*>(&d2);
}

// ---------------- path score: point_score + trans_score per batch
__global__ void path_kernel(const float* __restrict__ y,
                            const float* __restrict__ trans,
                            const int* __restrict__ labels, int T) {
    int b = blockIdx.x;
    int tid = threadIdx.x;           // 128 threads
    const int* lb = labels + (size_t)b * T;
    const float* yb = y + (size_t)b * T * KLAB;
    float s = 0.0f;
    for (int t = tid; t < T; t += blockDim.x) {
        int l0 = lb[t];
        s += yb[(size_t)t * KLAB + l0];
        if (t + 1 < T) s += trans[l0 * KLAB + lb[t + 1]];
    }
#pragma unroll
    for (int o = 16; o; o >>= 1) s += __shfl_xor_sync(0xffffffffu, s, o);
    __shared__ float ws[4];
    if ((tid & 31) == 0) ws[tid >> 5] = s;
    __syncthreads();
    if (tid == 0) g_path[b] = (ws[0] + ws[1]) + (ws[2] + ws[3]);
}

// ---------------- main forward recursion: 1 CTA per batch, thread j owns column j,
// D[:,j] resident in 128 bf16x2 registers, p broadcast from SMEM.
__global__ void __launch_bounds__(256, 1)
crf_kernel(const float* __restrict__ y, float* __restrict__ out, int T) {
    const int b = blockIdx.x;
    const int j = threadIdx.x;
    const int wid = j >> 5, lane = j & 31;

    __shared__ __align__(16) __nv_bfloat16 pbuf[2][KLAB];
    __shared__ __align__(16) float wsum[2][8];

    const float* yb = y + (size_t)b * T * KLAB;

    // Load D column j into registers (coalesced: stride KLAB over k)
    uint32_t dk[DPAIRS];
#pragma unroll
    for (int k = 0; k < DPAIRS; ++k) dk[k] = g_Dp[k * KLAB + j];

    // ---- init: state^(1) = y[b,0,:], reference r = y[b,0,0]
    float x00 = __ldg(yb);
    float x0j = __ldg(yb + j);
    float p1  = __expf(x0j - x00);
    pbuf[1][j] = __float2bfloat16(p1);
    {
        float w = p1;
#pragma unroll
        for (int o = 16; o; o >>= 1) w += __shfl_xor_sync(0xffffffffu, w, o);
        if (lane == 0) wsum[1][wid] = w;
    }
    float r = x00;

    // x prefetch pipeline (2 steps deep)
    float x_cur = __ldg(yb + KLAB + j);
    float x0c   = __ldg(yb + KLAB);
    float x_nxt = (T > 2) ? __ldg(yb + 2 * (size_t)KLAB + j) : 0.0f;
    float x0n   = (T > 2) ? __ldg(yb + 2 * (size_t)KLAB)     : 0.0f;

    __syncthreads();

    const __nv_bfloat162 z2 = __float2bfloat162_rn(0.0f);

    for (int t = 1; t < T; ++t) {
        const int buf  = t & 1;
        const int nbuf = buf ^ 1;

        // S_t = sum of 8 warp partial sums (double-buffered)
        const float4* w4 = reinterpret_cast<const float4*>(wsum[buf]);
        float4 wa = w4[0], wb = w4[1];
        float S = ((wa.x + wa.y) + (wa.z + wa.w)) + ((wb.x + wb.y) + (wb.z + wb.w));

        // C_j = sum_i p_i * D[i][j]  (bf16x2 HFMA2, 4 independent accumulators)
        const uint4* pb = reinterpret_cast<const uint4*>(pbuf[buf]);
        __nv_bfloat162 a0 = z2, a1 = z2, a2 = z2, a3 = z2;
#pragma unroll
        for (int m = 0; m < 32; ++m) {
            uint4 v = pb[m];                      // 8 p values, broadcast LDS.128
            a0 = __hfma2(as_bf2(dk[4 * m + 0]), as_bf2(v.x), a0);
            a1 = __hfma2(as_bf2(dk[4 * m + 1]), as_bf2(v.y), a1);
            a2 = __hfma2(as_bf2(dk[4 * m + 2]), as_bf2(v.z), a2);
            a3 = __hfma2(as_bf2(dk[4 * m + 3]), as_bf2(v.w), a3);
        }
        __nv_bfloat162 aa = __hadd2(__hadd2(a0, a1), __hadd2(a2, a3));
        float2 cf = __bfloat1622float2(aa);
        float C = cf.x + cf.y;

        // p'_j = (1 + C_j/S) * exp(x_tj - x_t0);  r += log S + x_t0
        float q    = __fdividef(C, S) + 1.0f;      // q in [0.948, 1.053] -- always > 0
        float pnew = q * __expf(x_cur - x0c);
        r += __logf(S) + x0c;

        pbuf[nbuf][j] = __float2bfloat16(pnew);
        float w = pnew;
#pragma unroll
        for (int o = 16; o; o >>= 1) w += __shfl_xor_sync(0xffffffffu, w, o);
        if (lane == 0) wsum[nbuf][wid] = w;

        // rotate x pipeline, prefetch t+2
        x_cur = x_nxt; x0c = x0n;
        int tf = t + 2;
        if (tf < T) {
            x_nxt = __ldg(yb + (size_t)tf * KLAB + j);
            x0n   = __ldg(yb + (size_t)tf * KLAB);
        }
        __syncthreads();
    }

    if (j == 0) {
        const float4* w4 = reinterpret_cast<const float4*>(wsum[T & 1]);
        float4 wa = w4[0], wb = w4[1];
        float S = ((wa.x + wa.y) + (wa.z + wa.w)) + ((wb.x + wb.y) + (wb.z + wb.w));
        out[b] = r + __logf(S) - g_path[b];
    }
}

// ---------------- launch
extern "C" void kernel_launch(void* const* d_in, const int* in_sizes, int n_in,
                              void* d_out, int out_size) {
    const float* y      = (const float*)d_in[0];   // (B,T,K) f32
    const float* trans  = (const float*)d_in[1];   // (K,K)   f32
    const int*   labels = (const int*)d_in[2];     // (B,T)   i32
    float* out = (float*)d_out;                    // (B,1)   f32

    int B = out_size;
    int T = in_sizes[0] / (B * KLAB);

    prep_kernel<<<(DPAIRS * KLAB + 511) / 512, 512>>>(trans);
    path_kernel<<<B, 128>>>(y, trans, labels, T);
    crf_kernel<<<B, 256>>>(y, out, T);
}

// round 2
// speedup vs baseline: 1.0957x; 1.0957x over previous
#include <cuda_runtime.h>
#include <cuda_bf16.h>
#include <stdint.h>

#define KLAB 256
#define DPAIRS 128   // 128 bf16x2 pairs (i-rows) per column

// E matrix, bf16x2-packed: g_Ep[k*KLAB + j] holds (exp(trans[2k][j]), exp(trans[2k+1][j]))
__device__ uint32_t g_Ep[DPAIRS * KLAB];
__device__ float    g_path[64];

static __device__ __forceinline__ __nv_bfloat162 as_bf2(uint32_t u) {
    return *reinterpret_cast<__nv_bfloat162*>(&u);
}

// ---------------- prep: E = exp(trans), packed bf16x2, k-major for coalesced column loads
__global__ void prep_kernel(const float* __restrict__ trans) {
    int idx = blockIdx.x * blockDim.x + threadIdx.x;   // 32768 total
    if (idx >= DPAIRS * KLAB) return;
    int k = idx >> 8;        // pair index (rows 2k, 2k+1)
    int j = idx & (KLAB - 1);
    float a = __expf(trans[(2 * k) * KLAB + j]);
    float b = __expf(trans[(2 * k + 1) * KLAB + j]);
    __nv_bfloat162 d2 = __floats2bfloat162_rn(a, b);   // .x = row 2k (low half)
    g_Ep[idx] = *reinterpret_cast<uint32_t*>(&d2);
}

// ---------------- path score: point_score + trans_score per batch
__global__ void path_kernel(const float* __restrict__ y,
                            const float* __restrict__ trans,
                            const int* __restrict__ labels, int T) {
    int b = blockIdx.x;
    int tid = threadIdx.x;           // 128 threads
    const int* lb = labels + (size_t)b * T;
    const float* yb = y + (size_t)b * T * KLAB;
    float s = 0.0f;
    for (int t = tid; t < T; t += blockDim.x) {
        int l0 = lb[t];
        s += yb[(size_t)t * KLAB + l0];
        if (t + 1 < T) s += trans[l0 * KLAB + lb[t + 1]];
    }
#pragma unroll
    for (int o = 16; o; o >>= 1) s += __shfl_xor_sync(0xffffffffu, s, o);
    __shared__ float ws[4];
    if ((tid & 31) == 0) ws[tid >> 5] = s;
    __syncthreads();
    if (tid == 0) g_path[b] = (ws[0] + ws[1]) + (ws[2] + ws[3]);
}

// ---------------- main forward recursion: 1 CTA per batch, thread j owns column j.
// E[:,j] resident in 128 bf16x2 registers; q broadcast from SMEM; no per-step
// reduction: normalization uses lag-1 scalar rho = q_0 from previous step.
__global__ void __launch_bounds__(256, 1)
crf_kernel(const float* __restrict__ y, float* __restrict__ out, int T) {
    const int b = blockIdx.x;
    const int j = threadIdx.x;
    const int wid = j >> 5, lane = j & 31;

    __shared__ __align__(16) __nv_bfloat16 pbuf[2][KLAB];
    __shared__ float rho[2];
    __shared__ float wsumF[8];

    const float* yb = y + (size_t)b * T * KLAB;

    // Load E column j into registers (coalesced: stride KLAB over k)
    uint32_t dk[DPAIRS];
#pragma unroll
    for (int k = 0; k < DPAIRS; ++k) dk[k] = g_Ep[k * KLAB + j];

    // ---- init: state^(0) = y[b,0,:], reference r = y[b,0,0]
    float x00 = __ldg(yb);
    float x0j = __ldg(yb + j);
    float pnew = __expf(x0j - x00);
    pbuf[1][j] = __float2bfloat16(pnew);
    if (j == 0) rho[1] = 1.0f;
    float r = x00;

    // x prefetch pipeline (2 steps deep)
    float x_cur = __ldg(yb + KLAB + j);
    float x0c   = __ldg(yb + KLAB);
    float x_nxt = (T > 2) ? __ldg(yb + 2 * (size_t)KLAB + j) : 0.0f;
    float x0n   = (T > 2) ? __ldg(yb + 2 * (size_t)KLAB)     : 0.0f;

    __syncthreads();

    const __nv_bfloat162 z2 = __float2bfloat162_rn(0.0f);

    for (int t = 1; t < T; ++t) {
        const int buf  = t & 1;
        const int nbuf = buf ^ 1;

        // off-critical-path scalars: scale = exp(x_j - x_0)/rho, logrho
        float rh = rho[buf];
        float sc = __fdividef(__expf(x_cur - x0c), rh);
        float lr = __logf(rh) + x0c;

        // C_j = sum_i q_i * E[i][j]  (bf16x2 HFMA2, 8 independent accumulators)
        const uint4* pb = reinterpret_cast<const uint4*>(pbuf[buf]);
        __nv_bfloat162 a0 = z2, a1 = z2, a2 = z2, a3 = z2;
        __nv_bfloat162 a4 = z2, a5 = z2, a6 = z2, a7 = z2;
#pragma unroll
        for (int m = 0; m < 32; m += 2) {
            uint4 v = pb[m];                      // 8 q values, broadcast LDS.128
            a0 = __hfma2(as_bf2(dk[4 * m + 0]), as_bf2(v.x), a0);
            a1 = __hfma2(as_bf2(dk[4 * m + 1]), as_bf2(v.y), a1);
            a2 = __hfma2(as_bf2(dk[4 * m + 2]), as_bf2(v.z), a2);
            a3 = __hfma2(as_bf2(dk[4 * m + 3]), as_bf2(v.w), a3);
            uint4 u = pb[m + 1];
            a4 = __hfma2(as_bf2(dk[4 * m + 4]), as_bf2(u.x), a4);
            a5 = __hfma2(as_bf2(dk[4 * m + 5]), as_bf2(u.y), a5);
            a6 = __hfma2(as_bf2(dk[4 * m + 6]), as_bf2(u.z), a6);
            a7 = __hfma2(as_bf2(dk[4 * m + 7]), as_bf2(u.w), a7);
        }
        // fp32 final combine of the 8 bf16x2 partials
        float2 f0 = __bfloat1622float2(a0);
        float2 f1 = __bfloat1622float2(a1);
        float2 f2 = __bfloat1622float2(a2);
        float2 f3 = __bfloat1622float2(a3);
        float2 f4 = __bfloat1622float2(a4);
        float2 f5 = __bfloat1622float2(a5);
        float2 f6 = __bfloat1622float2(a6);
        float2 f7 = __bfloat1622float2(a7);
        float C = ((f0.x + f0.y) + (f1.x + f1.y)) + ((f2.x + f2.y) + (f3.x + f3.y))
                + ((f4.x + f4.y) + (f5.x + f5.y)) + ((f6.x + f6.y) + (f7.x + f7.y));

        // q'_j = C_j * exp(x_j - x_0) / rho ;  r += x_0 + log rho
        pnew = C * sc;
        r += lr;

        pbuf[nbuf][j] = __float2bfloat16(pnew);
        if (j == 0) rho[nbuf] = pnew;

        // rotate x pipeline, prefetch t+2
        x_cur = x_nxt; x0c = x0n;
        int tf = t + 2;
        if (tf < T) {
            x_nxt = __ldg(yb + (size_t)tf * KLAB + j);
            x0n   = __ldg(yb + (size_t)tf * KLAB);
        }
        __syncthreads();
    }

    // final: log_norm = r + log(sum_j q_j);  one-time reduction
    float w = pnew;
#pragma unroll
    for (int o = 16; o; o >>= 1) w += __shfl_xor_sync(0xffffffffu, w, o);
    if (lane == 0) wsumF[wid] = w;
    __syncthreads();
    if (j == 0) {
        float S = ((wsumF[0] + wsumF[1]) + (wsumF[2] + wsumF[3]))
                + ((wsumF[4] + wsumF[5]) + (wsumF[6] + wsumF[7]));
        out[b] = r + __logf(S) - g_path[b];
    }
}

// ---------------- launch
extern "C" void kernel_launch(void* const* d_in, const int* in_sizes, int n_in,
                              void* d_out, int out_size) {
    const float* y      = (const float*)d_in[0];   // (B,T,K) f32
    const float* trans  = (const float*)d_in[1];   // (K,K)   f32
    const int*   labels = (const int*)d_in[2];     // (B,T)   i32
    float* out = (float*)d_out;                    // (B,1)   f32

    int B = out_size;
    int T = in_sizes[0] / (B * KLAB);

    prep_kernel<<<(DPAIRS * KLAB + 511) / 512, 512>>>(trans);
    path_kernel<<<B, 128>>>(y, trans, labels, T);
    crf_kernel<<<B, 256>>>(y, out, T);
}